// round 6
// baseline (speedup 1.0000x reference)
#include <cuda_runtime.h>

#define NQ      14
#define DIM     16384      // 2^14
#define NPAIR   8192       // DIM/2
#define NLAYERS 2
#define NTHR    1024
#define NGATES  (NLAYERS * NQ)

struct cpx { float x, y; };

__device__ __forceinline__ cpx cmul(cpx a, cpx b) {
    return { a.x * b.x - a.y * b.y, a.x * b.y + a.y * b.x };
}
__device__ __forceinline__ cpx cadd(cpx a, cpx b) {
    return { a.x + b.x, a.y + b.y };
}
__device__ __forceinline__ void mmul2(const cpx* A, const cpx* B, cpx* C) {
    C[0] = cadd(cmul(A[0], B[0]), cmul(A[1], B[2]));
    C[1] = cadd(cmul(A[0], B[1]), cmul(A[1], B[3]));
    C[2] = cadd(cmul(A[2], B[0]), cmul(A[3], B[2]));
    C[3] = cadd(cmul(A[2], B[1]), cmul(A[3], B[3]));
}

__global__ __launch_bounds__(NTHR, 1)
void qsim_kernel(const float* __restrict__ x,
                 const float* __restrict__ thetas,
                 float* __restrict__ out) {
    extern __shared__ float smem[];
    float* re = smem;          // [DIM]
    float* im = smem + DIM;    // [DIM]
    __shared__ cpx  gates[NGATES][4];
    __shared__ float red[32];

    const int b   = blockIdx.x;
    const int tid = threadIdx.x;
    const float xb = x[b];

    // ---- init state |0...0> ----
    for (int k = tid; k < DIM; k += NTHR) { re[k] = 0.0f; im[k] = 0.0f; }
    if (tid == 0) re[0] = 1.0f;

    // ---- precompute fused single-qubit gates: one thread per (layer, q) ----
    // G = RX(t2) * RZ(t1) * RX(t0) * RZ(x2) * RY(x1)
    if (tid < NGATES) {
        const int layer = tid / NQ;
        const int q     = tid % NQ;

        const float x1 = asinf(xb);
        const float x2 = acosf(xb * xb);
        float s1, c1;  sincosf(0.5f * x1, &s1, &c1);
        float sz, cz;  sincosf(0.5f * x2, &sz, &cz);
        // M = RZ(x2) * RY(x1)
        cpx M[4] = { { cz * c1, -sz * c1 }, { -cz * s1,  sz * s1 },
                     { cz * s1,  sz * s1 }, {  cz * c1,  sz * c1 } };

        const float* th = thetas + (layer * NQ + q) * 3;
        float s0, c0;   sincosf(0.5f * th[0], &s0, &c0);
        float sr1, cr1; sincosf(0.5f * th[1], &sr1, &cr1);
        float s2, c2v;  sincosf(0.5f * th[2], &s2, &c2v);

        cpx RX0[4] = { { c0, 0.f }, { 0.f, -s0 }, { 0.f, -s0 }, { c0, 0.f } };
        cpx RZ1[4] = { { cr1, -sr1 }, { 0.f, 0.f }, { 0.f, 0.f }, { cr1, sr1 } };
        cpx RX2[4] = { { c2v, 0.f }, { 0.f, -s2 }, { 0.f, -s2 }, { c2v, 0.f } };

        cpx T1[4], T2[4], G[4];
        mmul2(RX0, M,  T1);
        mmul2(RZ1, T1, T2);
        mmul2(RX2, T2, G);
        gates[tid][0] = G[0]; gates[tid][1] = G[1];
        gates[tid][2] = G[2]; gates[tid][3] = G[3];
    }
    __syncthreads();

    // ---- circuit ----
    for (int layer = 0; layer < NLAYERS; layer++) {
        // 14 fused single-qubit gates
        for (int q = 0; q < NQ; q++) {
            const cpx g0 = gates[layer * NQ + q][0];
            const cpx g1 = gates[layer * NQ + q][1];
            const cpx g2 = gates[layer * NQ + q][2];
            const cpx g3 = gates[layer * NQ + q][3];
            const int s      = NQ - 1 - q;     // bit position of qubit q
            const int stride = 1 << s;

            #pragma unroll 4
            for (int p = tid; p < NPAIR; p += NTHR) {
                const int i0 = ((p >> s) << (s + 1)) | (p & (stride - 1));
                const int i1 = i0 + stride;
                const cpx a  = { re[i0], im[i0] };
                const cpx bb = { re[i1], im[i1] };
                const cpx na = cadd(cmul(g0, a), cmul(g1, bb));
                const cpx nb = cadd(cmul(g2, a), cmul(g3, bb));
                re[i0] = na.x; im[i0] = na.y;
                re[i1] = nb.x; im[i1] = nb.y;
            }
            __syncthreads();
        }

        // fused CNOT chain: out[i] = in[i ^ (i >> 1)]
        float tr[DIM / NTHR], ti[DIM / NTHR];
        #pragma unroll
        for (int k = 0; k < DIM / NTHR; k++) {
            const int i   = tid + k * NTHR;
            const int src = i ^ (i >> 1);
            tr[k] = re[src]; ti[k] = im[src];
        }
        __syncthreads();
        #pragma unroll
        for (int k = 0; k < DIM / NTHR; k++) {
            const int i = tid + k * NTHR;
            re[i] = tr[k]; im[i] = ti[k];
        }
        __syncthreads();
    }

    // ---- expectation <Z...Z> = sum_i parity(i) * |amp_i|^2 ----
    float acc = 0.0f;
    #pragma unroll
    for (int k = 0; k < DIM / NTHR; k++) {
        const int i = tid + k * NTHR;
        const float p2 = re[i] * re[i] + im[i] * im[i];
        acc += (__popc(i) & 1) ? -p2 : p2;
    }
    #pragma unroll
    for (int o = 16; o; o >>= 1) acc += __shfl_down_sync(0xffffffffu, acc, o);
    if ((tid & 31) == 0) red[tid >> 5] = acc;
    __syncthreads();
    if (tid < 32) {
        float v = red[tid];
        #pragma unroll
        for (int o = 16; o; o >>= 1) v += __shfl_down_sync(0xffffffffu, v, o);
        if (tid == 0) out[b] = v;
    }
}

extern "C" void kernel_launch(void* const* d_in, const int* in_sizes, int n_in,
                              void* d_out, int out_size) {
    const float* x      = (const float*)d_in[0];
    const float* thetas = (const float*)d_in[1];
    float* out          = (float*)d_out;

    const int smem_bytes = 2 * DIM * (int)sizeof(float);  // 131072
    cudaFuncSetAttribute(qsim_kernel,
                         cudaFuncAttributeMaxDynamicSharedMemorySize, smem_bytes);
    qsim_kernel<<<64, NTHR, smem_bytes>>>(x, thetas, out);
}

// round 7
// speedup vs baseline: 1.0298x; 1.0298x over previous
#include <cuda_runtime.h>

#define NQ      14
#define DIM     16384      // 2^14
#define NPAIR   8192       // DIM/2
#define NLAYERS 2
#define NTHR    1024
#define NGATES  (NLAYERS * NQ)

struct cpx { float x, y; };

__device__ __forceinline__ cpx cmul(cpx a, cpx b) {
    return { a.x * b.x - a.y * b.y, a.x * b.y + a.y * b.x };
}
__device__ __forceinline__ cpx cadd(cpx a, cpx b) {
    return { a.x + b.x, a.y + b.y };
}
__device__ __forceinline__ void mmul2(const cpx* A, const cpx* B, cpx* C) {
    C[0] = cadd(cmul(A[0], B[0]), cmul(A[1], B[2]));
    C[1] = cadd(cmul(A[0], B[1]), cmul(A[1], B[3]));
    C[2] = cadd(cmul(A[2], B[0]), cmul(A[3], B[2]));
    C[3] = cadd(cmul(A[2], B[1]), cmul(A[3], B[3]));
}

__global__ __launch_bounds__(NTHR, 1)
void qsim_kernel(const float* __restrict__ x,
                 const float* __restrict__ thetas,
                 float* __restrict__ out) {
    extern __shared__ float smem[];
    float* re = smem;          // [DIM]
    float* im = smem + DIM;    // [DIM]
    __shared__ cpx  gates[NGATES][4];
    __shared__ float red[32];

    const int b   = blockIdx.x;
    const int tid = threadIdx.x;
    const float xb = x[b];

    // ---- init state |0...0> ----
    for (int k = tid; k < DIM; k += NTHR) { re[k] = 0.0f; im[k] = 0.0f; }
    if (tid == 0) re[0] = 1.0f;

    // ---- precompute fused single-qubit gates: one thread per (layer, q) ----
    // G = RX(t2) * RZ(t1) * RX(t0) * RZ(x2) * RY(x1)
    if (tid < NGATES) {
        const int layer = tid / NQ;
        const int q     = tid % NQ;

        const float x1 = asinf(xb);
        const float x2 = acosf(xb * xb);
        float s1, c1;  sincosf(0.5f * x1, &s1, &c1);
        float sz, cz;  sincosf(0.5f * x2, &sz, &cz);
        // M = RZ(x2) * RY(x1)
        cpx M[4] = { { cz * c1, -sz * c1 }, { -cz * s1,  sz * s1 },
                     { cz * s1,  sz * s1 }, {  cz * c1,  sz * c1 } };

        const float* th = thetas + (layer * NQ + q) * 3;
        float s0, c0;   sincosf(0.5f * th[0], &s0, &c0);
        float sr1, cr1; sincosf(0.5f * th[1], &sr1, &cr1);
        float s2, c2v;  sincosf(0.5f * th[2], &s2, &c2v);

        cpx RX0[4] = { { c0, 0.f }, { 0.f, -s0 }, { 0.f, -s0 }, { c0, 0.f } };
        cpx RZ1[4] = { { cr1, -sr1 }, { 0.f, 0.f }, { 0.f, 0.f }, { cr1, sr1 } };
        cpx RX2[4] = { { c2v, 0.f }, { 0.f, -s2 }, { 0.f, -s2 }, { c2v, 0.f } };

        cpx T1[4], T2[4], G[4];
        mmul2(RX0, M,  T1);
        mmul2(RZ1, T1, T2);
        mmul2(RX2, T2, G);
        gates[tid][0] = G[0]; gates[tid][1] = G[1];
        gates[tid][2] = G[2]; gates[tid][3] = G[3];
    }
    __syncthreads();

    // ---- circuit ----
    for (int layer = 0; layer < NLAYERS; layer++) {
        // 14 fused single-qubit gates
        for (int q = 0; q < NQ; q++) {
            const cpx g0 = gates[layer * NQ + q][0];
            const cpx g1 = gates[layer * NQ + q][1];
            const cpx g2 = gates[layer * NQ + q][2];
            const cpx g3 = gates[layer * NQ + q][3];
            const int s      = NQ - 1 - q;     // bit position of qubit q
            const int stride = 1 << s;

            #pragma unroll 4
            for (int p = tid; p < NPAIR; p += NTHR) {
                const int i0 = ((p >> s) << (s + 1)) | (p & (stride - 1));
                const int i1 = i0 + stride;
                const cpx a  = { re[i0], im[i0] };
                const cpx bb = { re[i1], im[i1] };
                const cpx na = cadd(cmul(g0, a), cmul(g1, bb));
                const cpx nb = cadd(cmul(g2, a), cmul(g3, bb));
                re[i0] = na.x; im[i0] = na.y;
                re[i1] = nb.x; im[i1] = nb.y;
            }
            __syncthreads();
        }

        // fused CNOT chain: out[i] = in[i ^ (i >> 1)]
        float tr[DIM / NTHR], ti[DIM / NTHR];
        #pragma unroll
        for (int k = 0; k < DIM / NTHR; k++) {
            const int i   = tid + k * NTHR;
            const int src = i ^ (i >> 1);
            tr[k] = re[src]; ti[k] = im[src];
        }
        __syncthreads();
        #pragma unroll
        for (int k = 0; k < DIM / NTHR; k++) {
            const int i = tid + k * NTHR;
            re[i] = tr[k]; im[i] = ti[k];
        }
        __syncthreads();
    }

    // ---- expectation <Z...Z> = sum_i parity(i) * |amp_i|^2 ----
    float acc = 0.0f;
    #pragma unroll
    for (int k = 0; k < DIM / NTHR; k++) {
        const int i = tid + k * NTHR;
        const float p2 = re[i] * re[i] + im[i] * im[i];
        acc += (__popc(i) & 1) ? -p2 : p2;
    }
    #pragma unroll
    for (int o = 16; o; o >>= 1) acc += __shfl_down_sync(0xffffffffu, acc, o);
    if ((tid & 31) == 0) red[tid >> 5] = acc;
    __syncthreads();
    if (tid < 32) {
        float v = red[tid];
        #pragma unroll
        for (int o = 16; o; o >>= 1) v += __shfl_down_sync(0xffffffffu, v, o);
        if (tid == 0) out[b] = v;
    }
}

extern "C" void kernel_launch(void* const* d_in, const int* in_sizes, int n_in,
                              void* d_out, int out_size) {
    const float* x      = (const float*)d_in[0];
    const float* thetas = (const float*)d_in[1];
    float* out          = (float*)d_out;

    const int smem_bytes = 2 * DIM * (int)sizeof(float);  // 131072
    cudaFuncSetAttribute(qsim_kernel,
                         cudaFuncAttributeMaxDynamicSharedMemorySize, smem_bytes);
    qsim_kernel<<<64, NTHR, smem_bytes>>>(x, thetas, out);
}